// round 2
// baseline (speedup 1.0000x reference)
#include <cuda_runtime.h>
#include <math.h>
#include <float.h>

// Problem constants: B=8, Z=4, X=32, Y=32, N=4096
#define NPTS    4096
#define NB      8
#define TA      512      // prep kernel threads
#define TB      1024     // nms kernel threads
#define NWARPB  (TB / 32)
#define MAXKEEP 64
#define CUT     2.0f

// NMS kernel dynamic smem: 7 arrays of NPTS + warp scratch + kept arrays
#define SMEMB ((7 * NPTS + 2 * NWARPB + 4 * MAXKEEP) * 4)

// Scratch SoA written by prep kernel (1 MB total, L2-resident for nms kernel)
__device__ float4 g_pred4[NB][NPTS];   // (conf | -FLT_MAX, p0, p1, p2) normalized
__device__ float4 g_targ4[NB][NPTS];   // (active, t0|1e30, t1, t2) real coords

__device__ __forceinline__ float row_angle(float ax, float ay, float az,
                                           float bx, float by, float bz) {
    float na = sqrtf(ax * ax + ay * ay + az * az);
    float nb = sqrtf(bx * bx + by * by + bz * bz);
    float c = (ax * bx + ay * by + az * bz) / (na * nb);
    c = fminf(1.0f, fmaxf(-1.0f, c));
    return (acosf(c) / 3.14159265358979323846f) * 180.0f;
}

// ---- Kernel A: wide transform, DRAM -> SoA scratch ----
__global__ __launch_bounds__(TA, 2)
void prep_kernel(const float* __restrict__ pred, const float* __restrict__ targ) {
    int b = blockIdx.x >> 3;
    int n = ((blockIdx.x & 7) << 9) | threadIdx.x;
    const float* p = pred + ((long long)b * NPTS + n) * 10;
    const float* t = targ + ((long long)b * NPTS + n) * 10;
    // 40-byte pitch is 8-byte aligned for every n -> float2 loads legal
    float2 p01 = *(const float2*)p;
    float2 p23 = *(const float2*)(p + 2);
    float2 t01 = *(const float2*)t;
    float2 t23 = *(const float2*)(t + 2);
    float z = (float)(n >> 10), x = (float)((n >> 5) & 31), y = (float)(n & 31);
    float4 o;
    // sigmoid(c) > 0.5  <=>  c > 0  (exact)
    o.x = (p01.x > 0.0f) ? p01.x : -FLT_MAX;
    o.y = (p01.y + z) * 0.25f;      // /Z=4 exact
    o.z = (p23.x + x) * 0.03125f;   // /X=32 exact
    o.w = (p23.y + y) * 0.03125f;   // /Y=32 exact
    g_pred4[b][n] = o;
    float4 q;
    bool act = t01.x > 0.5f;
    q.x = act ? 1.0f : 0.0f;
    // inactive target -> position sentinel so distance tests auto-fail
    q.y = act ? ((t01.y + z) * 0.25f) * 25.0f : 1e30f;
    q.z = ((t23.x + x) * 0.03125f) * 25.0f;
    q.w = ((t23.y + y) * 0.03125f) * 4.0f;
    g_targ4[b][n] = q;
}

// ---- Kernel B: per-batch greedy NMS + matching (scratch is L2-hot) ----
__global__ __launch_bounds__(TB, 1)
void nms_kernel(const float* __restrict__ pred,
                const float* __restrict__ targ,
                float* __restrict__ out) {
    extern __shared__ float sm[];
    float* s_conf = sm;                 // [NPTS]
    float* s_p0 = s_conf + NPTS;
    float* s_p1 = s_p0 + NPTS;
    float* s_p2 = s_p1 + NPTS;
    float* s_t0 = s_p2 + NPTS;          // real coords (1e30 = inactive)
    float* s_t1 = s_t0 + NPTS;
    float* s_t2 = s_t1 + NPTS;
    float* wv = s_t2 + NPTS;            // [NWARPB]
    int* wi = (int*)(wv + NWARPB);      // [NWARPB]
    float* kx = (float*)(wi + NWARPB);
    float* ky = kx + MAXKEEP;
    float* kz = ky + MAXKEEP;
    int* kid = (int*)(kz + MAXKEEP);

    __shared__ int sK, sSel, sTP, sNTG;
    __shared__ float sAng;
    __shared__ float selp[3];

    const int tid = threadIdx.x;
    const int lane = tid & 31;
    const int warp = tid >> 5;
    const int b = blockIdx.x;

    // ---- Load SoA scratch (LDG.128, L2-resident) + count active targets ----
    int cnt = 0;
    for (int n = tid; n < NPTS; n += TB) {
        float4 o = g_pred4[b][n];
        s_conf[n] = o.x; s_p0[n] = o.y; s_p1[n] = o.z; s_p2[n] = o.w;
        float4 q = g_targ4[b][n];
        cnt += (q.x > 0.5f) ? 1 : 0;
        s_t0[n] = q.y; s_t1[n] = q.z; s_t2[n] = q.w;
    }
    #pragma unroll
    for (int o = 16; o; o >>= 1) cnt += __shfl_down_sync(0xffffffffu, cnt, o);
    if (lane == 0) wi[warp] = cnt;
    if (tid == 0) { sK = 0; sTP = 0; sAng = 0.0f; }
    __syncthreads();
    if (tid == 0) {
        int s = 0;
        for (int w = 0; w < NWARPB; w++) s += wi[w];
        sNTG = s;
    }
    __syncthreads();

    // ---- Greedy NMS (== converged iterative suppression of the reference) ----
    for (;;) {
        float bv = -FLT_MAX;
        int bi = 0x7fffffff;
        for (int n = tid; n < NPTS; n += TB) {
            float v = s_conf[n];
            if (v > bv) { bv = v; bi = n; }
        }
        #pragma unroll
        for (int o = 16; o; o >>= 1) {
            float v2 = __shfl_down_sync(0xffffffffu, bv, o);
            int i2 = __shfl_down_sync(0xffffffffu, bi, o);
            if (v2 > bv || (v2 == bv && i2 < bi)) { bv = v2; bi = i2; }
        }
        if (lane == 0) { wv[warp] = bv; wi[warp] = bi; }
        __syncthreads();
        if (warp == 0) {
            float v = wv[lane];
            int i = wi[lane];
            #pragma unroll
            for (int o = 16; o; o >>= 1) {
                float v2 = __shfl_down_sync(0xffffffffu, v, o);
                int i2 = __shfl_down_sync(0xffffffffu, i, o);
                if (v2 > v || (v2 == v && i2 < i)) { v = v2; i = i2; }
            }
            if (lane == 0) {
                if (v == -FLT_MAX || sK >= MAXKEEP) {
                    sSel = -1;
                } else {
                    sSel = i;
                    int K = sK;
                    kx[K] = s_p0[i]; ky[K] = s_p1[i]; kz[K] = s_p2[i]; kid[K] = i;
                    selp[0] = s_p0[i]; selp[1] = s_p1[i]; selp[2] = s_p2[i];
                    sK = K + 1;
                }
            }
        }
        __syncthreads();
        if (sSel < 0) break;
        float c0 = selp[0], c1 = selp[1], c2 = selp[2];
        for (int n = tid; n < NPTS; n += TB) {
            if (s_conf[n] != -FLT_MAX) {
                float d0 = s_p0[n] - c0, d1 = s_p1[n] - c1, d2 = s_p2[n] - c2;
                float ss = (d0 * d0 + d1 * d1) + d2 * d2;
                if (sqrtf(ss) < CUT) s_conf[n] = -FLT_MAX;
            }
        }
        __syncthreads();
    }

    // ---- Per kept pred: first in-range active target; accumulate angles ----
    const int K = sK;
    const float* P = pred + (long long)b * NPTS * 10;
    const float* T = targ + (long long)b * NPTS * 10;
    for (int k = 0; k < K; k++) {
        float q0 = kx[k] * 25.0f, q1 = ky[k] * 25.0f, q2 = kz[k] * 4.0f;
        int best = 0x7fffffff;
        for (int t = tid; t < NPTS; t += TB) {
            float d0 = s_t0[t] - q0, d1 = s_t1[t] - q1, d2 = s_t2[t] - q2;
            float ss = (d0 * d0 + d1 * d1) + d2 * d2;
            if (sqrtf(ss) < CUT && t < best) best = t;  // sentinel 1e30 auto-fails
        }
        #pragma unroll
        for (int o = 16; o; o >>= 1) {
            int v2 = __shfl_down_sync(0xffffffffu, best, o);
            if (v2 < best) best = v2;
        }
        if (lane == 0) wi[warp] = best;
        __syncthreads();
        if (tid == 0) {
            int bmin = 0x7fffffff;
            for (int w = 0; w < NWARPB; w++) if (wi[w] < bmin) bmin = wi[w];
            if (bmin != 0x7fffffff) {
                sTP += 1;
                int i = kid[k];
                const float* p = P + (long long)i * 10;
                const float* t = T + (long long)bmin * 10;
                float ax = p[4], ay = p[5], az = p[6];
                float bx = p[7], by = p[8], bz = p[9];
                float cx = ay * bz - az * by;
                float cy = az * bx - ax * bz;
                float cz = ax * by - ay * bx;
                float tax = t[4], tay = t[5], taz = t[6];
                float tbx = t[7], tby = t[8], tbz = t[9];
                float tcx = tay * tbz - taz * tby;
                float tcy = taz * tbx - tax * tbz;
                float tcz = tax * tby - tay * tbx;
                sAng += row_angle(ax, ay, az, tax, tay, taz)
                      + row_angle(bx, by, bz, tbx, tby, tbz)
                      + row_angle(cx, cy, cz, tcx, tcy, tcz);
            }
        }
        __syncthreads();
    }

    if (tid == 0) {
        float tp = (float)sTP;
        out[b * 3 + 0] = tp;
        out[b * 3 + 1] = (float)K - tp;
        out[b * 3 + 2] = (float)sNTG - tp;
        out[3 * NB + b] = (sTP > 0) ? (sAng / (3.0f * tp)) : 0.0f;
    }
}

extern "C" void kernel_launch(void* const* d_in, const int* in_sizes, int n_in,
                              void* d_out, int out_size) {
    const float* pred = (const float*)d_in[0];
    const float* targ = (const float*)d_in[1];
    float* out = (float*)d_out;
    cudaFuncSetAttribute(nms_kernel, cudaFuncAttributeMaxDynamicSharedMemorySize,
                         SMEMB);
    prep_kernel<<<NB * 8, TA>>>(pred, targ);
    nms_kernel<<<NB, TB, SMEMB>>>(pred, targ, out);
}

// round 3
// speedup vs baseline: 1.0952x; 1.0952x over previous
#include <cuda_runtime.h>
#include <math.h>
#include <float.h>

// Problem constants: B=8, Z=4, X=32, Y=32, N=4096
#define NPTS   4096
#define NB     8
#define T      1024
#define NW     (T / 32)
#define MAXK   16
#define CHUNK  1024
#define NCH    (NPTS / CHUNK)
#define ITER   (NPTS / T)          // 4 smem elems per thread
#define CUT    2.0f

// smem layout (floats):
//  s_conf[4096] s_p0[4096] s_p1[4096] s_p2[4096]   pred SoA (normalized)
//  s_t0[4096] s_t1[4096] s_t2[4096]                targ real coords (1e30 = inactive)
//  SP[10240] ST[10240]                              raw staging (one 1024-pt chunk each)
//  wv[32] wi[32] m_best[16*32] + kept/match scratch
#define SM_FLOATS (7 * NPTS + 2 * CHUNK * 10 + 2 * NW + MAXK * NW + 8 * MAXK + 16)
#define SMEM_BYTES (SM_FLOATS * 4)

__device__ __forceinline__ float row_angle(float ax, float ay, float az,
                                           float bx, float by, float bz) {
    float na = sqrtf(ax * ax + ay * ay + az * az);
    float nb = sqrtf(bx * bx + by * by + bz * bz);
    float c = (ax * bx + ay * by + az * bz) / (na * nb);
    c = fminf(1.0f, fmaxf(-1.0f, c));
    return (acosf(c) / 3.14159265358979323846f) * 180.0f;
}

__global__ __launch_bounds__(T, 1)
void mol_kernel(const float* __restrict__ pred,
                const float* __restrict__ targ,
                float* __restrict__ out) {
    extern __shared__ float sm[];
    float* s_conf = sm;
    float* s_p0 = s_conf + NPTS;
    float* s_p1 = s_p0 + NPTS;
    float* s_p2 = s_p1 + NPTS;
    float* s_t0 = s_p2 + NPTS;
    float* s_t1 = s_t0 + NPTS;
    float* s_t2 = s_t1 + NPTS;
    float* SP = s_t2 + NPTS;            // [CHUNK*10]
    float* ST = SP + CHUNK * 10;        // [CHUNK*10]
    float* wv = ST + CHUNK * 10;        // [NW]
    int* wi = (int*)(wv + NW);          // [NW]
    int* m_best = (int*)(wi + NW);      // [MAXK*NW]
    float* krx = (float*)(m_best + MAXK * NW);  // kept real coords
    float* kry = krx + MAXK;
    float* krz = kry + MAXK;
    int* kid = (int*)(krz + MAXK);      // kept original indices
    int* sMatch = kid + MAXK;           // matched target per kept
    float* sAngArr = (float*)(sMatch + MAXK);
    int* sHit = (int*)(sAngArr + MAXK);
    float* selp = (float*)(sHit + MAXK);  // [3] + flags after

    __shared__ int sK, sSel, sNTG;

    const int tid = threadIdx.x;
    const int lane = tid & 31;
    const int warp = tid >> 5;
    const int b = blockIdx.x;

    // ---- Phase 1: coalesced staged load + parse ----
    int cnt = 0;
    for (int c = 0; c < NCH; c++) {
        const float4* gp = (const float4*)(pred + ((size_t)b * NPTS + c * CHUNK) * 10);
        const float4* gt = (const float4*)(targ + ((size_t)b * NPTS + c * CHUNK) * 10);
        float4* sp4 = (float4*)SP;
        float4* st4 = (float4*)ST;
        #pragma unroll
        for (int i = tid; i < CHUNK * 10 / 4; i += T) {
            sp4[i] = gp[i];
            st4[i] = gt[i];
        }
        __syncthreads();
        int n = c * CHUNK + tid;
        float z = (float)(n >> 10), x = (float)((n >> 5) & 31), y = (float)(n & 31);
        const float* p = SP + tid * 10;
        const float* t = ST + tid * 10;
        float pc = p[0];
        s_conf[n] = (pc > 0.0f) ? pc : -FLT_MAX;     // sigmoid>0.5 <=> raw>0
        s_p0[n] = (p[1] + z) * 0.25f;                // /Z=4 exact
        s_p1[n] = (p[2] + x) * 0.03125f;             // /X=32 exact
        s_p2[n] = (p[3] + y) * 0.03125f;             // /Y=32 exact
        bool act = t[0] > 0.5f;
        cnt += act ? 1 : 0;
        s_t0[n] = act ? ((t[1] + z) * 0.25f) * 25.0f : 1e30f;  // sentinel kills dist test
        s_t1[n] = ((t[2] + x) * 0.03125f) * 25.0f;
        s_t2[n] = ((t[3] + y) * 0.03125f) * 4.0f;
        __syncthreads();
    }

    // active-target count
    #pragma unroll
    for (int o = 16; o; o >>= 1) cnt += __shfl_down_sync(0xffffffffu, cnt, o);
    if (lane == 0) wi[warp] = cnt;
    if (tid == 0) {
        sK = 0;
        selp[0] = 1e30f; selp[1] = 1e30f; selp[2] = 1e30f;   // round 0: no suppression
    }
    __syncthreads();
    if (tid == 0) {
        int s = 0;
        for (int w = 0; w < NW; w++) s += wi[w];
        sNTG = s;
    }
    __syncthreads();

    // ---- Phase 2: greedy NMS, suppression fused into argmax scan (2 bars/round) ----
    for (;;) {
        float c0 = selp[0], c1 = selp[1], c2 = selp[2];
        float bv = -FLT_MAX;
        int bi = 0x7fffffff;
        #pragma unroll
        for (int j = 0; j < ITER; j++) {
            int n = j * T + tid;
            float v = s_conf[n];
            if (v != -FLT_MAX) {
                float d0 = s_p0[n] - c0, d1 = s_p1[n] - c1, d2 = s_p2[n] - c2;
                float ss = (d0 * d0 + d1 * d1) + d2 * d2;
                if (sqrtf(ss) < CUT) { s_conf[n] = -FLT_MAX; v = -FLT_MAX; }
            }
            if (v > bv) { bv = v; bi = n; }
        }
        #pragma unroll
        for (int o = 16; o; o >>= 1) {
            float v2 = __shfl_down_sync(0xffffffffu, bv, o);
            int i2 = __shfl_down_sync(0xffffffffu, bi, o);
            if (v2 > bv || (v2 == bv && i2 < bi)) { bv = v2; bi = i2; }
        }
        if (lane == 0) { wv[warp] = bv; wi[warp] = bi; }
        __syncthreads();
        if (warp == 0) {
            float v = wv[lane];
            int i = wi[lane];
            #pragma unroll
            for (int o = 16; o; o >>= 1) {
                float v2 = __shfl_down_sync(0xffffffffu, v, o);
                int i2 = __shfl_down_sync(0xffffffffu, i, o);
                if (v2 > v || (v2 == v && i2 < i)) { v = v2; i = i2; }
            }
            if (lane == 0) {
                if (v == -FLT_MAX || sK >= MAXK) {
                    sSel = -1;
                } else {
                    int K = sK;
                    kid[K] = i;
                    krx[K] = s_p0[i] * 25.0f;
                    kry[K] = s_p1[i] * 25.0f;
                    krz[K] = s_p2[i] * 4.0f;
                    selp[0] = s_p0[i]; selp[1] = s_p1[i]; selp[2] = s_p2[i];
                    sK = K + 1;
                    sSel = i;
                }
            }
        }
        __syncthreads();
        if (sSel < 0) break;
    }

    // ---- Phase 3: single-pass matching over all kept preds ----
    const int K = sK;
    int best[MAXK];
    #pragma unroll
    for (int kk = 0; kk < MAXK; kk++) best[kk] = 0x7fffffff;
    #pragma unroll
    for (int j = 0; j < ITER; j++) {
        int n = j * T + tid;
        float a0 = s_t0[n], a1 = s_t1[n], a2 = s_t2[n];
        #pragma unroll
        for (int kk = 0; kk < MAXK; kk++) {
            if (kk < K) {
                float d0 = a0 - krx[kk], d1 = a1 - kry[kk], d2 = a2 - krz[kk];
                float ss = (d0 * d0 + d1 * d1) + d2 * d2;
                if (sqrtf(ss) < CUT && n < best[kk]) best[kk] = n;
            }
        }
    }
    #pragma unroll
    for (int kk = 0; kk < MAXK; kk++) {
        if (kk < K) {
            int v = best[kk];
            #pragma unroll
            for (int o = 16; o; o >>= 1) {
                int v2 = __shfl_down_sync(0xffffffffu, v, o);
                if (v2 < v) v = v2;
            }
            if (lane == 0) m_best[kk * NW + warp] = v;
        }
    }
    __syncthreads();
    if (warp < K) {   // warp k reduces kept-point k across warps
        int v = m_best[warp * NW + lane];
        #pragma unroll
        for (int o = 16; o; o >>= 1) {
            int v2 = __shfl_down_sync(0xffffffffu, v, o);
            if (v2 < v) v = v2;
        }
        if (lane == 0) sMatch[warp] = v;
    }
    __syncthreads();

    // ---- Phase 4: K parallel angle computations (rotation rows from global) ----
    if (tid < K) {
        int mt = sMatch[tid];
        if (mt != 0x7fffffff) {
            const float* p = pred + ((size_t)b * NPTS + kid[tid]) * 10 + 4;
            const float* t = targ + ((size_t)b * NPTS + mt) * 10 + 4;
            float2 pa = *(const float2*)p;         // offsets 4..9 are 8B aligned
            float2 pb = *(const float2*)(p + 2);
            float2 pc2 = *(const float2*)(p + 4);
            float2 ta = *(const float2*)t;
            float2 tb = *(const float2*)(t + 2);
            float2 tc2 = *(const float2*)(t + 4);
            float ax = pa.x, ay = pa.y, az = pb.x;
            float bx = pb.y, by = pc2.x, bz = pc2.y;
            float cx = ay * bz - az * by;
            float cy = az * bx - ax * bz;
            float cz = ax * by - ay * bx;
            float tax = ta.x, tay = ta.y, taz = tb.x;
            float tbx = tb.y, tby = tc2.x, tbz = tc2.y;
            float tcx = tay * tbz - taz * tby;
            float tcy = taz * tbx - tax * tbz;
            float tcz = tax * tby - tay * tbx;
            sAngArr[tid] = row_angle(ax, ay, az, tax, tay, taz)
                         + row_angle(bx, by, bz, tbx, tby, tbz)
                         + row_angle(cx, cy, cz, tcx, tcy, tcz);
            sHit[tid] = 1;
        } else {
            sAngArr[tid] = 0.0f;
            sHit[tid] = 0;
        }
    }
    __syncthreads();

    // ---- Phase 5: deterministic epilogue ----
    if (tid == 0) {
        int tp = 0;
        float ang = 0.0f;
        for (int k = 0; k < K; k++) { tp += sHit[k]; ang += sAngArr[k]; }
        float tpf = (float)tp;
        out[b * 3 + 0] = tpf;
        out[b * 3 + 1] = (float)K - tpf;
        out[b * 3 + 2] = (float)sNTG - tpf;
        out[3 * NB + b] = (tp > 0) ? (ang / (3.0f * tpf)) : 0.0f;
    }
}

extern "C" void kernel_launch(void* const* d_in, const int* in_sizes, int n_in,
                              void* d_out, int out_size) {
    const float* pred = (const float*)d_in[0];
    const float* targ = (const float*)d_in[1];
    float* out = (float*)d_out;
    cudaFuncSetAttribute(mol_kernel, cudaFuncAttributeMaxDynamicSharedMemorySize,
                         SMEM_BYTES);
    mol_kernel<<<NB, T, SMEM_BYTES>>>(pred, targ, out);
}